// round 1
// baseline (speedup 1.0000x reference)
#include <cuda_runtime.h>
#include <math.h>

#define NB   64
#define NC   256
#define HW   4096        // 64*64
#define HIDD 16
#define NCOND 32
#define RHID 64

// scratch (no allocations allowed)
__device__ float g_semantic[NB * NC];
__device__ float g_scale[NB * NC];

// ---------------------------------------------------------------------------
// Kernel 1: global average pool per (b,c) plane. 16384 blocks x 128 threads.
// Each thread reads 8 float4 (32 floats), 4096 floats per block.
// ---------------------------------------------------------------------------
__global__ void gap_kernel(const float* __restrict__ x) {
    const int bc = blockIdx.x;
    const float4* __restrict__ p =
        reinterpret_cast<const float4*>(x + (size_t)bc * HW);
    const int t = threadIdx.x;

    float s = 0.0f;
#pragma unroll
    for (int j = 0; j < 8; ++j) {
        float4 v = p[t + 128 * j];
        s += (v.x + v.y) + (v.z + v.w);
    }
#pragma unroll
    for (int o = 16; o > 0; o >>= 1)
        s += __shfl_down_sync(0xffffffffu, s, o);

    __shared__ float ws[4];
    if ((t & 31) == 0) ws[t >> 5] = s;
    __syncthreads();
    if (t == 0) {
        float tot = (ws[0] + ws[1]) + (ws[2] + ws[3]);
        g_semantic[bc] = tot * (1.0f / 4096.0f);
    }
}

// ---------------------------------------------------------------------------
// Kernel 2: per-batch tiny MLPs + top-k mask. 64 blocks x 256 threads.
// ---------------------------------------------------------------------------
__global__ void select_kernel(
    const float* __restrict__ base_cr,
    const float* __restrict__ embed,     // [3,16]
    const float* __restrict__ snr_w1,    // [16,1]
    const float* __restrict__ snr_b1,    // [16]
    const float* __restrict__ snr_w2,    // [16,16]
    const float* __restrict__ snr_b2,    // [16]
    const float* __restrict__ sem_w,     // [16,256]
    const float* __restrict__ cond_w,    // [16,32]
    const float* __restrict__ out_w,     // [256,16]
    const float* __restrict__ r_w1,      // [64,288]
    const float* __restrict__ r_b1,      // [64]
    const float* __restrict__ r_w2,      // [64,64]
    const float* __restrict__ r_b2,      // [64]
    const float* __restrict__ r_w3,      // [1,64]
    const float* __restrict__ r_b3,      // [1]
    const int*   __restrict__ channel_idx,
    const int*   __restrict__ snr_db,
    float* __restrict__ out_cr)
{
    const int b = blockIdx.x;
    const int t = threadIdx.x;

    __shared__ float sem[NC];
    __shared__ float cond[NCOND];
    __shared__ float fused[HIDD];
    __shared__ float w[NC];
    __shared__ float r1[RHID];
    __shared__ float r2[RHID];
    __shared__ int   k_sh;

    sem[t] = g_semantic[b * NC + t];

    if (t < HIDD) {
        cond[t] = embed[channel_idx[0] * 16 + t];
    }
    if (t >= 32 && t < 48) {
        const int i = t - 32;
        const float snr_norm = (float)snr_db[0] / 28.0f;
        float acc = snr_b2[i];
#pragma unroll
        for (int j = 0; j < 16; ++j) {
            float hj = fmaxf(snr_norm * snr_w1[j] + snr_b1[j], 0.0f);
            acc += hj * snr_w2[i * 16 + j];
        }
        cond[16 + i] = fmaxf(acc, 0.0f);
    }
    __syncthreads();

    // fused = relu(sem @ sem_w.T + cond @ cond_w.T)  [16]
    if (t < HIDD) {
        float acc = 0.0f;
        for (int c = 0; c < NC; ++c) acc += sem[c] * sem_w[t * NC + c];
        for (int j = 0; j < NCOND; ++j) acc += cond[j] * cond_w[t * NCOND + j];
        fused[t] = fmaxf(acc, 0.0f);
    }

    // rate controller layer 1 (only needs sem/cond)
    if (t < RHID) {
        float acc = r_b1[t];
        const float* __restrict__ wr = r_w1 + t * (NC + NCOND);
        for (int j = 0; j < NC; ++j) acc += sem[j] * wr[j];
        for (int j = 0; j < NCOND; ++j) acc += cond[j] * wr[NC + j];
        r1[t] = fmaxf(acc, 0.0f);
    }
    __syncthreads();

    // weights = sigmoid(fused @ out_w.T)  [256]
    {
        float acc = 0.0f;
#pragma unroll
        for (int h = 0; h < HIDD; ++h) acc += fused[h] * out_w[t * HIDD + h];
        w[t] = 1.0f / (1.0f + expf(-acc));
    }

    // rate controller layer 2
    if (t < RHID) {
        float acc = r_b2[t];
#pragma unroll
        for (int j = 0; j < RHID; ++j) acc += r1[j] * r_w2[t * RHID + j];
        r2[t] = fmaxf(acc, 0.0f);
    }
    __syncthreads();

    if (t == 0) {
        float acc = r_b3[0];
#pragma unroll
        for (int j = 0; j < RHID; ++j) acc += r2[j] * r_w3[j];
        float raw = 1.0f / (1.0f + expf(-acc));
        float dyn = 0.3f + 0.7f * raw;
        float cr  = 0.3f * base_cr[0] + 0.7f * dyn;
        cr = fminf(fmaxf(cr, 0.3f), 1.0f);
        out_cr[b] = cr;
        float crs = fminf(fmaxf(cr, 0.001f), 1.0f);
        int kk = (int)rintf(crs * 256.0f);   // round-half-even, matches jnp.round
        kk = min(max(kk, 1), 256);
        k_sh = kk;
    }
    __syncthreads();

    // rank of channel t in descending stable sort of w:
    // rank = #{j : w_j > w_t} + #{j < t : w_j == w_t}
    const float wc = w[t];
    int rank = 0;
    for (int j = 0; j < NC; ++j) {
        float wj = w[j];
        rank += (wj > wc) || (wj == wc && j < t);
    }
    g_scale[b * NC + t] = (rank < k_sh) ? 1.0f : 0.0f;
}

// ---------------------------------------------------------------------------
// Kernel 3: y = x * mask. 16384 blocks x 256 threads, float4.
// Dropped planes are write-only (skip the load entirely).
// ---------------------------------------------------------------------------
__global__ void apply_kernel(const float* __restrict__ x,
                             float* __restrict__ y) {
    const int bc = blockIdx.x;
    const float s = g_scale[bc];
    const int t = threadIdx.x;
    float4* __restrict__ yo =
        reinterpret_cast<float4*>(y + (size_t)bc * HW);

    if (s != 0.0f) {
        const float4* __restrict__ xi =
            reinterpret_cast<const float4*>(x + (size_t)bc * HW);
#pragma unroll
        for (int j = 0; j < 4; ++j)
            yo[t + 256 * j] = xi[t + 256 * j];
    } else {
        const float4 z = make_float4(0.0f, 0.0f, 0.0f, 0.0f);
#pragma unroll
        for (int j = 0; j < 4; ++j)
            yo[t + 256 * j] = z;
    }
}

// ---------------------------------------------------------------------------
extern "C" void kernel_launch(void* const* d_in, const int* in_sizes, int n_in,
                              void* d_out, int out_size) {
    const float* x       = (const float*)d_in[0];
    const float* base_cr = (const float*)d_in[1];
    const float* embed   = (const float*)d_in[2];
    const float* snr_w1  = (const float*)d_in[3];
    const float* snr_b1  = (const float*)d_in[4];
    const float* snr_w2  = (const float*)d_in[5];
    const float* snr_b2  = (const float*)d_in[6];
    const float* sem_w   = (const float*)d_in[7];
    const float* cond_w  = (const float*)d_in[8];
    const float* out_w   = (const float*)d_in[9];
    const float* r_w1    = (const float*)d_in[10];
    const float* r_b1    = (const float*)d_in[11];
    const float* r_w2    = (const float*)d_in[12];
    const float* r_b2    = (const float*)d_in[13];
    const float* r_w3    = (const float*)d_in[14];
    const float* r_b3    = (const float*)d_in[15];
    const int*   ch_idx  = (const int*)d_in[16];
    const int*   snr_db  = (const int*)d_in[17];

    float* y      = (float*)d_out;
    float* out_cr = y + (size_t)NB * NC * HW;   // cr_values appended after y

    gap_kernel<<<NB * NC, 128>>>(x);
    select_kernel<<<NB, 256>>>(base_cr, embed, snr_w1, snr_b1, snr_w2, snr_b2,
                               sem_w, cond_w, out_w,
                               r_w1, r_b1, r_w2, r_b2, r_w3, r_b3,
                               ch_idx, snr_db, out_cr);
    apply_kernel<<<NB * NC, 256>>>(x, y);
}

// round 2
// speedup vs baseline: 1.0135x; 1.0135x over previous
#include <cuda_runtime.h>
#include <math.h>

#define NB   64
#define NC   256
#define HW   4096        // 64*64
#define HIDD 16
#define NCOND 32
#define RHID 64
#define NPLANES (NB * NC)   // 16384

// scratch (no allocations allowed)
__device__ float g_semantic[NB * NC];
__device__ float g_scale[NB * NC];

// ---------------------------------------------------------------------------
// Kernel 1: global average pool per (b,c) plane. 16384 blocks x 128 threads.
// Default (evict-normal) loads: the tail of x stays LRU-resident in L2 so
// apply_kernel (reverse order) can hit it.
// ---------------------------------------------------------------------------
__global__ void gap_kernel(const float* __restrict__ x) {
    const int bc = blockIdx.x;
    const float4* __restrict__ p =
        reinterpret_cast<const float4*>(x + (size_t)bc * HW);
    const int t = threadIdx.x;

    float s = 0.0f;
#pragma unroll
    for (int j = 0; j < 8; ++j) {
        float4 v = p[t + 128 * j];
        s += (v.x + v.y) + (v.z + v.w);
    }
#pragma unroll
    for (int o = 16; o > 0; o >>= 1)
        s += __shfl_down_sync(0xffffffffu, s, o);

    __shared__ float ws[4];
    if ((t & 31) == 0) ws[t >> 5] = s;
    __syncthreads();
    if (t == 0) {
        float tot = (ws[0] + ws[1]) + (ws[2] + ws[3]);
        g_semantic[bc] = tot * (1.0f / 4096.0f);
    }
}

// ---------------------------------------------------------------------------
// Kernel 2: per-batch tiny MLPs + top-k mask. 64 blocks x 256 threads.
// ---------------------------------------------------------------------------
__global__ void select_kernel(
    const float* __restrict__ base_cr,
    const float* __restrict__ embed,     // [3,16]
    const float* __restrict__ snr_w1,    // [16,1]
    const float* __restrict__ snr_b1,    // [16]
    const float* __restrict__ snr_w2,    // [16,16]
    const float* __restrict__ snr_b2,    // [16]
    const float* __restrict__ sem_w,     // [16,256]
    const float* __restrict__ cond_w,    // [16,32]
    const float* __restrict__ out_w,     // [256,16]
    const float* __restrict__ r_w1,      // [64,288]
    const float* __restrict__ r_b1,      // [64]
    const float* __restrict__ r_w2,      // [64,64]
    const float* __restrict__ r_b2,      // [64]
    const float* __restrict__ r_w3,      // [1,64]
    const float* __restrict__ r_b3,      // [1]
    const int*   __restrict__ channel_idx,
    const int*   __restrict__ snr_db,
    float* __restrict__ out_cr)
{
    const int b = blockIdx.x;
    const int t = threadIdx.x;

    __shared__ float sem[NC];
    __shared__ float cond[NCOND];
    __shared__ float fused[HIDD];
    __shared__ float w[NC];
    __shared__ float r1[RHID];
    __shared__ float r2[RHID];
    __shared__ int   k_sh;

    sem[t] = g_semantic[b * NC + t];

    if (t < HIDD) {
        cond[t] = embed[channel_idx[0] * 16 + t];
    }
    if (t >= 32 && t < 48) {
        const int i = t - 32;
        const float snr_norm = (float)snr_db[0] / 28.0f;
        float acc = snr_b2[i];
#pragma unroll
        for (int j = 0; j < 16; ++j) {
            float hj = fmaxf(snr_norm * snr_w1[j] + snr_b1[j], 0.0f);
            acc += hj * snr_w2[i * 16 + j];
        }
        cond[16 + i] = fmaxf(acc, 0.0f);
    }
    __syncthreads();

    // fused = relu(sem @ sem_w.T + cond @ cond_w.T)  [16]
    if (t < HIDD) {
        float acc = 0.0f;
        for (int c = 0; c < NC; ++c) acc += sem[c] * sem_w[t * NC + c];
        for (int j = 0; j < NCOND; ++j) acc += cond[j] * cond_w[t * NCOND + j];
        fused[t] = fmaxf(acc, 0.0f);
    }

    // rate controller layer 1 (only needs sem/cond)
    if (t < RHID) {
        float acc = r_b1[t];
        const float* __restrict__ wr = r_w1 + t * (NC + NCOND);
        for (int j = 0; j < NC; ++j) acc += sem[j] * wr[j];
        for (int j = 0; j < NCOND; ++j) acc += cond[j] * wr[NC + j];
        r1[t] = fmaxf(acc, 0.0f);
    }
    __syncthreads();

    // weights = sigmoid(fused @ out_w.T)  [256]
    {
        float acc = 0.0f;
#pragma unroll
        for (int h = 0; h < HIDD; ++h) acc += fused[h] * out_w[t * HIDD + h];
        w[t] = 1.0f / (1.0f + expf(-acc));
    }

    // rate controller layer 2
    if (t < RHID) {
        float acc = r_b2[t];
#pragma unroll
        for (int j = 0; j < RHID; ++j) acc += r1[j] * r_w2[t * RHID + j];
        r2[t] = fmaxf(acc, 0.0f);
    }
    __syncthreads();

    if (t == 0) {
        float acc = r_b3[0];
#pragma unroll
        for (int j = 0; j < RHID; ++j) acc += r2[j] * r_w3[j];
        float raw = 1.0f / (1.0f + expf(-acc));
        float dyn = 0.3f + 0.7f * raw;
        float cr  = 0.3f * base_cr[0] + 0.7f * dyn;
        cr = fminf(fmaxf(cr, 0.3f), 1.0f);
        out_cr[b] = cr;
        float crs = fminf(fmaxf(cr, 0.001f), 1.0f);
        int kk = (int)rintf(crs * 256.0f);   // round-half-even, matches jnp.round
        kk = min(max(kk, 1), 256);
        k_sh = kk;
    }
    __syncthreads();

    // rank of channel t in descending stable sort of w:
    // rank = #{j : w_j > w_t} + #{j < t : w_j == w_t}
    const float wc = w[t];
    int rank = 0;
    for (int j = 0; j < NC; ++j) {
        float wj = w[j];
        rank += (wj > wc) || (wj == wc && j < t);
    }
    g_scale[b * NC + t] = (rank < k_sh) ? 1.0f : 0.0f;
}

// ---------------------------------------------------------------------------
// Kernel 3: y = x * mask. 16384 blocks x 256 threads, float4.
// Planes processed in REVERSE order: first-scheduled blocks touch the planes
// gap_kernel read last (still LRU-resident in L2 -> hits instead of DRAM).
// x loads are evict-first (dead after this), y stores are streaming
// (never re-read; keeps the x tail from being flushed out of L2).
// ---------------------------------------------------------------------------
__global__ void apply_kernel(const float* __restrict__ x,
                             float* __restrict__ y) {
    const int bc = (NPLANES - 1) - blockIdx.x;
    const float s = g_scale[bc];
    const int t = threadIdx.x;
    float4* __restrict__ yo =
        reinterpret_cast<float4*>(y + (size_t)bc * HW);

    if (s != 0.0f) {
        const float4* __restrict__ xi =
            reinterpret_cast<const float4*>(x + (size_t)bc * HW);
#pragma unroll
        for (int j = 0; j < 4; ++j) {
            float4 v = __ldcs(&xi[t + 256 * j]);
            __stcs(&yo[t + 256 * j], v);
        }
    } else {
        const float4 z = make_float4(0.0f, 0.0f, 0.0f, 0.0f);
#pragma unroll
        for (int j = 0; j < 4; ++j)
            __stcs(&yo[t + 256 * j], z);
    }
}

// ---------------------------------------------------------------------------
extern "C" void kernel_launch(void* const* d_in, const int* in_sizes, int n_in,
                              void* d_out, int out_size) {
    const float* x       = (const float*)d_in[0];
    const float* base_cr = (const float*)d_in[1];
    const float* embed   = (const float*)d_in[2];
    const float* snr_w1  = (const float*)d_in[3];
    const float* snr_b1  = (const float*)d_in[4];
    const float* snr_w2  = (const float*)d_in[5];
    const float* snr_b2  = (const float*)d_in[6];
    const float* sem_w   = (const float*)d_in[7];
    const float* cond_w  = (const float*)d_in[8];
    const float* out_w   = (const float*)d_in[9];
    const float* r_w1    = (const float*)d_in[10];
    const float* r_b1    = (const float*)d_in[11];
    const float* r_w2    = (const float*)d_in[12];
    const float* r_b2    = (const float*)d_in[13];
    const float* r_w3    = (const float*)d_in[14];
    const float* r_b3    = (const float*)d_in[15];
    const int*   ch_idx  = (const int*)d_in[16];
    const int*   snr_db  = (const int*)d_in[17];

    float* y      = (float*)d_out;
    float* out_cr = y + (size_t)NB * NC * HW;   // cr_values appended after y

    gap_kernel<<<NB * NC, 128>>>(x);
    select_kernel<<<NB, 256>>>(base_cr, embed, snr_w1, snr_b1, snr_w2, snr_b2,
                               sem_w, cond_w, out_w,
                               r_w1, r_b1, r_w2, r_b2, r_w3, r_b3,
                               ch_idx, snr_db, out_cr);
    apply_kernel<<<NB * NC, 256>>>(x, y);
}

// round 3
// speedup vs baseline: 1.0345x; 1.0207x over previous
#include <cuda_runtime.h>
#include <math.h>

#define NB    64
#define NC    256
#define HW    4096          // 64*64
#define NPLANES (NB * NC)   // 16384
#define NPAIRS  (NPLANES / 2)
#define HIDD  16
#define NCOND 32
#define RHID  64
#define TPB   256
#define GRID  888           // 148 SMs x 6 blocks, all resident in wave 1

// ---- scratch (no allocations allowed) ----
__device__ float g_semantic[NPLANES];
__device__ float g_scale[NPLANES];
__device__ int   g_gap_ctr;
__device__ int   g_apply_ctr;
__device__ int   g_batch_done[NB];
__device__ int   g_ready[NB];

struct Sm {
    float red[8];
    float sem[NC];
    float cond[NCOND];
    float fusedv[HIDD];
    float w[NC];
    float r1[RHID];
    float r2[RHID];
    int   bc_pair;   // broadcast: grabbed pair index
    int   bc_flag;   // broadcast: select-needed / ready / help-pair
    int   k;
};

// ---------------------------------------------------------------------------
__global__ void init_kernel() {
    const int t = threadIdx.x;
    if (t == 0) { g_gap_ctr = 0; g_apply_ctr = 0; }
    if (t < NB) { g_batch_done[t] = 0; g_ready[t] = 0; }
}

// ---------------------------------------------------------------------------
// block-wide sum of one 4096-float plane; result valid on t==0
__device__ __forceinline__ float plane_sum(const float* __restrict__ x,
                                           int p, int t, float* red) {
    const float4* __restrict__ pp =
        reinterpret_cast<const float4*>(x + (size_t)p * HW);
    float s = 0.0f;
#pragma unroll
    for (int j = 0; j < 4; ++j) {
        float4 v = pp[t + 256 * j];
        s += (v.x + v.y) + (v.z + v.w);
    }
#pragma unroll
    for (int o = 16; o > 0; o >>= 1)
        s += __shfl_down_sync(0xffffffffu, s, o);
    if ((t & 31) == 0) red[t >> 5] = s;
    __syncthreads();
    float tot = 0.0f;
    if (t == 0) {
#pragma unroll
        for (int i = 0; i < 8; ++i) tot += red[i];
    }
    __syncthreads();          // red[] reusable afterwards
    return tot;
}

// ---------------------------------------------------------------------------
// full select for batch b, executed by one whole block (256 threads)
__device__ __forceinline__ void do_select(
    int b, int t, Sm& sm,
    const float* __restrict__ base_cr,
    const float* __restrict__ embed,  const float* __restrict__ snr_w1,
    const float* __restrict__ snr_b1, const float* __restrict__ snr_w2,
    const float* __restrict__ snr_b2, const float* __restrict__ sem_w,
    const float* __restrict__ cond_w, const float* __restrict__ out_w,
    const float* __restrict__ r_w1,   const float* __restrict__ r_b1,
    const float* __restrict__ r_w2,   const float* __restrict__ r_b2,
    const float* __restrict__ r_w3,   const float* __restrict__ r_b3,
    const int*   __restrict__ channel_idx, const int* __restrict__ snr_db,
    float* __restrict__ out_cr)
{
    sm.sem[t] = __ldcg(&g_semantic[b * NC + t]);

    if (t < HIDD) sm.cond[t] = embed[channel_idx[0] * 16 + t];
    if (t >= 32 && t < 48) {
        const int i = t - 32;
        const float snr_norm = (float)snr_db[0] / 28.0f;
        float acc = snr_b2[i];
#pragma unroll
        for (int j = 0; j < 16; ++j) {
            float hj = fmaxf(snr_norm * snr_w1[j] + snr_b1[j], 0.0f);
            acc += hj * snr_w2[i * 16 + j];
        }
        sm.cond[16 + i] = fmaxf(acc, 0.0f);
    }
    __syncthreads();

    if (t < HIDD) {
        float acc = 0.0f;
        for (int c = 0; c < NC; ++c)    acc += sm.sem[c]  * sem_w[t * NC + c];
        for (int j = 0; j < NCOND; ++j) acc += sm.cond[j] * cond_w[t * NCOND + j];
        sm.fusedv[t] = fmaxf(acc, 0.0f);
    }
    if (t < RHID) {
        float acc = r_b1[t];
        const float* __restrict__ wr = r_w1 + t * (NC + NCOND);
        for (int j = 0; j < NC; ++j)    acc += sm.sem[j]  * wr[j];
        for (int j = 0; j < NCOND; ++j) acc += sm.cond[j] * wr[NC + j];
        sm.r1[t] = fmaxf(acc, 0.0f);
    }
    __syncthreads();

    {
        float acc = 0.0f;
#pragma unroll
        for (int h = 0; h < HIDD; ++h) acc += sm.fusedv[h] * out_w[t * HIDD + h];
        sm.w[t] = 1.0f / (1.0f + expf(-acc));
    }
    if (t < RHID) {
        float acc = r_b2[t];
#pragma unroll
        for (int j = 0; j < RHID; ++j) acc += sm.r1[j] * r_w2[t * RHID + j];
        sm.r2[t] = fmaxf(acc, 0.0f);
    }
    __syncthreads();

    if (t == 0) {
        float acc = r_b3[0];
#pragma unroll
        for (int j = 0; j < RHID; ++j) acc += sm.r2[j] * r_w3[j];
        float raw = 1.0f / (1.0f + expf(-acc));
        float dyn = 0.3f + 0.7f * raw;
        float cr  = 0.3f * base_cr[0] + 0.7f * dyn;
        cr = fminf(fmaxf(cr, 0.3f), 1.0f);
        out_cr[b] = cr;
        float crs = fminf(fmaxf(cr, 0.001f), 1.0f);
        int kk = (int)rintf(crs * 256.0f);   // round-half-even == jnp.round
        kk = min(max(kk, 1), 256);
        sm.k = kk;
    }
    __syncthreads();

    // stable descending rank
    const float wc = sm.w[t];
    int rank = 0;
    for (int j = 0; j < NC; ++j) {
        float wj = sm.w[j];
        rank += (wj > wc) || (wj == wc && j < t);
    }
    g_scale[b * NC + t] = (rank < sm.k) ? 1.0f : 0.0f;
    __syncthreads();
}

// ---------------------------------------------------------------------------
// gap one pair of planes (same batch), trigger select if batch completes
__device__ __forceinline__ void gap_pair(
    int pr, int t, Sm& sm, const float* __restrict__ x,
    const float* __restrict__ base_cr,
    const float* __restrict__ embed,  const float* __restrict__ snr_w1,
    const float* __restrict__ snr_b1, const float* __restrict__ snr_w2,
    const float* __restrict__ snr_b2, const float* __restrict__ sem_w,
    const float* __restrict__ cond_w, const float* __restrict__ out_w,
    const float* __restrict__ r_w1,   const float* __restrict__ r_b1,
    const float* __restrict__ r_w2,   const float* __restrict__ r_b2,
    const float* __restrict__ r_w3,   const float* __restrict__ r_b3,
    const int*   __restrict__ channel_idx, const int* __restrict__ snr_db,
    float* __restrict__ out_cr)
{
    const int p0 = pr * 2;
    const int b  = p0 >> 8;           // pair never crosses a batch (256 even)

    float s0 = plane_sum(x, p0,     t, sm.red);
    float s1 = plane_sum(x, p0 + 1, t, sm.red);
    if (t == 0) {
        g_semantic[p0]     = s0 * (1.0f / 4096.0f);
        g_semantic[p0 + 1] = s1 * (1.0f / 4096.0f);
        __threadfence();                       // release semantics stores
        int old = atomicAdd(&g_batch_done[b], 2);
        int need_sel = (old == 254);
        if (need_sel) __threadfence();         // acquire others' stores
        sm.bc_flag = need_sel;
    }
    __syncthreads();
    if (sm.bc_flag) {
        __syncthreads();
        do_select(b, t, sm, base_cr, embed, snr_w1, snr_b1, snr_w2, snr_b2,
                  sem_w, cond_w, out_w, r_w1, r_b1, r_w2, r_b2, r_w3, r_b3,
                  channel_idx, snr_db, out_cr);
        if (t == 0) {
            __threadfence();                   // release g_scale / out_cr
            atomicExch(&g_ready[b], 1);
        }
    }
    __syncthreads();
}

// ---------------------------------------------------------------------------
__global__ void __launch_bounds__(TPB, 6) fused_kernel(
    const float* __restrict__ x,
    const float* __restrict__ base_cr,
    const float* __restrict__ embed,  const float* __restrict__ snr_w1,
    const float* __restrict__ snr_b1, const float* __restrict__ snr_w2,
    const float* __restrict__ snr_b2, const float* __restrict__ sem_w,
    const float* __restrict__ cond_w, const float* __restrict__ out_w,
    const float* __restrict__ r_w1,   const float* __restrict__ r_b1,
    const float* __restrict__ r_w2,   const float* __restrict__ r_b2,
    const float* __restrict__ r_w3,   const float* __restrict__ r_b3,
    const int*   __restrict__ channel_idx, const int* __restrict__ snr_db,
    float* __restrict__ y, float* __restrict__ out_cr)
{
    __shared__ Sm sm;
    const int t = threadIdx.x;

#define GAP_ARGS x, base_cr, embed, snr_w1, snr_b1, snr_w2, snr_b2, sem_w, \
                 cond_w, out_w, r_w1, r_b1, r_w2, r_b2, r_w3, r_b3,        \
                 channel_idx, snr_db, out_cr

    // ---- producer role: even blocks drain the gap queue first ----
    if ((blockIdx.x & 1) == 0) {
        for (;;) {
            if (t == 0) sm.bc_pair = atomicAdd(&g_gap_ctr, 1);
            __syncthreads();
            const int pr = sm.bc_pair;
            __syncthreads();
            if (pr >= NPAIRS) break;
            gap_pair(pr, t, sm, GAP_ARGS);
        }
    }

    // ---- consumer role: apply planes in order, helping gap while waiting ----
    for (;;) {
        if (t == 0) sm.bc_pair = atomicAdd(&g_apply_ctr, 1);
        __syncthreads();
        const int qr = sm.bc_pair;
        __syncthreads();
        if (qr >= NPAIRS) break;
        const int p0 = qr * 2;
        const int b  = p0 >> 8;

        // wait for the batch's mask; contribute to gap instead of spinning
        for (;;) {
            int hp;
            if (t == 0) {
                if (atomicAdd(&g_ready[b], 0) != 0) {
                    __threadfence();           // acquire g_scale
                    hp = -2;                   // ready
                } else {
                    int g = atomicAdd(&g_gap_ctr, 1);
                    hp = (g < NPAIRS) ? g : -1;
                }
                sm.bc_flag = hp;
            }
            __syncthreads();
            hp = sm.bc_flag;
            __syncthreads();
            if (hp == -2) break;
            if (hp >= 0)  gap_pair(hp, t, sm, GAP_ARGS);
            else if (t == 0) __nanosleep(200);
        }

        // apply the two planes
#pragma unroll
        for (int pl = p0; pl < p0 + 2; ++pl) {
            const float s = __ldcg(&g_scale[pl]);
            float4* __restrict__ yo =
                reinterpret_cast<float4*>(y + (size_t)pl * HW);
            if (s != 0.0f) {
                const float4* __restrict__ xi =
                    reinterpret_cast<const float4*>(x + (size_t)pl * HW);
#pragma unroll
                for (int j = 0; j < 4; ++j) {
                    float4 v = __ldcs(&xi[t + 256 * j]);
                    __stcs(&yo[t + 256 * j], v);
                }
            } else {
                const float4 z = make_float4(0.f, 0.f, 0.f, 0.f);
#pragma unroll
                for (int j = 0; j < 4; ++j)
                    __stcs(&yo[t + 256 * j], z);
            }
        }
        __syncthreads();
    }
#undef GAP_ARGS
}

// ---------------------------------------------------------------------------
extern "C" void kernel_launch(void* const* d_in, const int* in_sizes, int n_in,
                              void* d_out, int out_size) {
    const float* x       = (const float*)d_in[0];
    const float* base_cr = (const float*)d_in[1];
    const float* embed   = (const float*)d_in[2];
    const float* snr_w1  = (const float*)d_in[3];
    const float* snr_b1  = (const float*)d_in[4];
    const float* snr_w2  = (const float*)d_in[5];
    const float* snr_b2  = (const float*)d_in[6];
    const float* sem_w   = (const float*)d_in[7];
    const float* cond_w  = (const float*)d_in[8];
    const float* out_w   = (const float*)d_in[9];
    const float* r_w1    = (const float*)d_in[10];
    const float* r_b1    = (const float*)d_in[11];
    const float* r_w2    = (const float*)d_in[12];
    const float* r_b2    = (const float*)d_in[13];
    const float* r_w3    = (const float*)d_in[14];
    const float* r_b3    = (const float*)d_in[15];
    const int*   ch_idx  = (const int*)d_in[16];
    const int*   snr_db  = (const int*)d_in[17];

    float* y      = (float*)d_out;
    float* out_cr = y + (size_t)NPLANES * HW;   // cr_values appended after y

    init_kernel<<<1, 64>>>();
    fused_kernel<<<GRID, TPB>>>(x, base_cr, embed, snr_w1, snr_b1, snr_w2,
                                snr_b2, sem_w, cond_w, out_w,
                                r_w1, r_b1, r_w2, r_b2, r_w3, r_b3,
                                ch_idx, snr_db, y, out_cr);
}